// round 8
// baseline (speedup 1.0000x reference)
#include <cuda_runtime.h>
#include <math.h>
#include <stdint.h>

#define PATCH 7
#define PP 49

#define BM 32
#define BN 64
#define BK 16
#define AS_S 20        // A smem row stride (words), conflict-free for frag loads
#define BS_S 72        // B smem row stride (words), conflict-free for frag loads

// Scratch
__device__ float g_act0[1 << 18];    // activations ping (1024*256)
__device__ float g_act1[1 << 18];    // activations pong
__device__ float g_whi[1 << 18];     // 4 layers x 256x256 tf32-hi
__device__ float g_wlo[1 << 18];     // 4 layers x 256x256 tf32-lo

__device__ __forceinline__ uint32_t f32_to_tf32(float x) {
    uint32_t r;
    asm("cvt.rna.tf32.f32 %0, %1;" : "=r"(r) : "f"(x));
    return r;
}

__device__ __forceinline__ void mma_tf32(float* c, const uint32_t* a, const uint32_t* b) {
    asm volatile(
        "mma.sync.aligned.m16n8k8.row.col.f32.tf32.tf32.f32 "
        "{%0,%1,%2,%3}, {%4,%5,%6,%7}, {%8,%9}, {%0,%1,%2,%3};\n"
        : "+f"(c[0]), "+f"(c[1]), "+f"(c[2]), "+f"(c[3])
        : "r"(a[0]), "r"(a[1]), "r"(a[2]), "r"(a[3]), "r"(b[0]), "r"(b[1]));
}

// ---------------------------------------------------------------------------
// Prep: decompose all 4 weight matrices into tf32 hi/lo parts.
// 65536 threads, one float4 each over 4*256*256 floats.
// ---------------------------------------------------------------------------
__global__ void __launch_bounds__(256)
prep_kernel(const float* __restrict__ W0, const float* __restrict__ W1,
            const float* __restrict__ W2, const float* __restrict__ W3,
            float* __restrict__ whi, float* __restrict__ wlo) {
    const int idx4 = blockIdx.x * blockDim.x + threadIdx.x;   // 0..65535
    const int l = idx4 >> 14;                                  // 16384 float4 per layer
    const int e = idx4 & 16383;
    const float* W = (l == 0) ? W0 : (l == 1) ? W1 : (l == 2) ? W2 : W3;
    float4 w = reinterpret_cast<const float4*>(W)[e];
    float4 hi, lo;
    hi.x = __uint_as_float(f32_to_tf32(w.x));
    hi.y = __uint_as_float(f32_to_tf32(w.y));
    hi.z = __uint_as_float(f32_to_tf32(w.z));
    hi.w = __uint_as_float(f32_to_tf32(w.w));
    lo.x = __uint_as_float(f32_to_tf32(w.x - hi.x));
    lo.y = __uint_as_float(f32_to_tf32(w.y - hi.y));
    lo.z = __uint_as_float(f32_to_tf32(w.z - hi.z));
    lo.w = __uint_as_float(f32_to_tf32(w.w - hi.w));
    reinterpret_cast<float4*>(whi)[idx4] = hi;
    reinterpret_cast<float4*>(wlo)[idx4] = lo;
}

// ---------------------------------------------------------------------------
// 3xTF32 tensor-core GEMM + bias (+ReLU): C[M,N] = A[M,K] @ W[K,N] + b
// BM=32, BN=64, BK=16, 128 threads (4 warps). Warp w: m-tile (w&1)*16,
// n-tile (w>>1)*32. Per k8-step per warp: 4 n8 frags x 3 mma (hi*hi, hi*lo,
// lo*hi). A decomposed on the fly; W pre-decomposed.
// ---------------------------------------------------------------------------
template <bool RELU>
__global__ void __launch_bounds__(128)
gemm_tf32_kernel(const float* __restrict__ A,
                 const float* __restrict__ Whi, const float* __restrict__ Wlo,
                 const float* __restrict__ bias, float* __restrict__ C,
                 int M, int N, int K) {
    __shared__ float As[2][BM][AS_S];
    __shared__ float Bh[2][BK][BS_S];
    __shared__ float Bl[2][BK][BS_S];

    const int tid = threadIdx.x;
    const int lane = tid & 31;
    const int wid = tid >> 5;
    const int block_m = blockIdx.y * BM;
    const int block_n = blockIdx.x * BN;

    const int warp_m = (wid & 1) * 16;
    const int warp_n = (wid >> 1) * 32;

    // A global load: row = tid>>2 (0..31), kc = (tid&3)*4
    const int a_row = tid >> 2;
    const int a_kc = (tid & 3) * 4;
    const size_t a_base = (size_t)(block_m + a_row) * K + a_kc;

    // B global load: kr = tid>>3 (0..15), nc = (tid&7)*8 -> 2 float4 (hi), 2 (lo)
    const int b_kr = tid >> 3;
    const int b_nc = (tid & 7) * 8;
    const size_t w_base = (size_t)b_kr * N + block_n + b_nc;

    float4 aR, bhR0, bhR1, blR0, blR1;

    auto g_load = [&](int t) {
        const size_t ko = (size_t)t * BK;
        aR = *reinterpret_cast<const float4*>(&A[a_base + ko]);
        bhR0 = *reinterpret_cast<const float4*>(&Whi[w_base + ko * N]);
        bhR1 = *reinterpret_cast<const float4*>(&Whi[w_base + ko * N + 4]);
        blR0 = *reinterpret_cast<const float4*>(&Wlo[w_base + ko * N]);
        blR1 = *reinterpret_cast<const float4*>(&Wlo[w_base + ko * N + 4]);
    };
    auto s_store = [&](int buf) {
        *reinterpret_cast<float4*>(&As[buf][a_row][a_kc]) = aR;
        *reinterpret_cast<float4*>(&Bh[buf][b_kr][b_nc]) = bhR0;
        *reinterpret_cast<float4*>(&Bh[buf][b_kr][b_nc + 4]) = bhR1;
        *reinterpret_cast<float4*>(&Bl[buf][b_kr][b_nc]) = blR0;
        *reinterpret_cast<float4*>(&Bl[buf][b_kr][b_nc + 4]) = blR1;
    };

    g_load(0);
    s_store(0);
    __syncthreads();

    float acc[4][4];
#pragma unroll
    for (int j = 0; j < 4; j++)
#pragma unroll
        for (int i = 0; i < 4; i++) acc[j][i] = 0.f;

    const int g = lane >> 2;        // group id (0..7)
    const int tg = lane & 3;        // thread-in-group (0..3)
    const int nt = K / BK;          // 16
    int cur = 0;

    for (int t = 0; t < nt; t++) {
        if (t + 1 < nt) g_load(t + 1);

#pragma unroll
        for (int kk = 0; kk < BK; kk += 8) {
            // A fragment: rows warp_m+g, warp_m+g+8; cols kk+tg, kk+tg+4
            uint32_t ahi[4], alo[4];
            {
                float a0 = As[cur][warp_m + g][kk + tg];
                float a1 = As[cur][warp_m + g + 8][kk + tg];
                float a2 = As[cur][warp_m + g][kk + tg + 4];
                float a3 = As[cur][warp_m + g + 8][kk + tg + 4];
                ahi[0] = f32_to_tf32(a0);
                ahi[1] = f32_to_tf32(a1);
                ahi[2] = f32_to_tf32(a2);
                ahi[3] = f32_to_tf32(a3);
                alo[0] = f32_to_tf32(a0 - __uint_as_float(ahi[0]));
                alo[1] = f32_to_tf32(a1 - __uint_as_float(ahi[1]));
                alo[2] = f32_to_tf32(a2 - __uint_as_float(ahi[2]));
                alo[3] = f32_to_tf32(a3 - __uint_as_float(ahi[3]));
            }
#pragma unroll
            for (int j = 0; j < 4; j++) {
                const int n = warp_n + j * 8 + g;
                uint32_t bhi[2], blo[2];
                bhi[0] = __float_as_uint(Bh[cur][kk + tg][n]);
                bhi[1] = __float_as_uint(Bh[cur][kk + tg + 4][n]);
                blo[0] = __float_as_uint(Bl[cur][kk + tg][n]);
                blo[1] = __float_as_uint(Bl[cur][kk + tg + 4][n]);
                mma_tf32(acc[j], ahi, bhi);
                mma_tf32(acc[j], ahi, blo);
                mma_tf32(acc[j], alo, bhi);
            }
        }

        if (t + 1 < nt) {
            s_store(cur ^ 1);
            __syncthreads();
            cur ^= 1;
        }
    }

    // Epilogue: bias + relu, float2 stores
    const int row0 = block_m + warp_m + g;
#pragma unroll
    for (int j = 0; j < 4; j++) {
        const int col = block_n + warp_n + j * 8 + 2 * tg;
        const float b0 = bias[col];
        const float b1 = bias[col + 1];
        float v0 = acc[j][0] + b0;
        float v1 = acc[j][1] + b1;
        float v2 = acc[j][2] + b0;
        float v3 = acc[j][3] + b1;
        if (RELU) {
            v0 = fmaxf(v0, 0.f);
            v1 = fmaxf(v1, 0.f);
            v2 = fmaxf(v2, 0.f);
            v3 = fmaxf(v3, 0.f);
        }
        *reinterpret_cast<float2*>(&C[(size_t)row0 * N + col]) = make_float2(v0, v1);
        *reinterpret_cast<float2*>(&C[(size_t)(row0 + 8) * N + col]) = make_float2(v2, v3);
    }
}

// ---------------------------------------------------------------------------
// Patch gather + dot + indices. One block (256 threads) per query.
// Output layout in d_out (float32):
//   [0, N*49)        logits (n, py, px)
//   [N*49, N*49*5)   indices as float (n, py, px, {b,y,x,q})
// ---------------------------------------------------------------------------
__global__ void __launch_bounds__(256)
patch_kernel(const float* __restrict__ fm, const float* __restrict__ qe,
             const float* __restrict__ qpos, const int* __restrict__ shapes,
             float* __restrict__ out, int N, int Q, int D) {
    __shared__ float sq[256];
    const int n = blockIdx.x;
    if (n >= N) return;

    const int b = n / Q;
    const int q = n - b * Q;
    const int Hb = shapes[2 * b + 0];
    const int Wb = shapes[2 * b + 1];

    const float posx = qpos[2 * n + 0];
    const float posy = qpos[2 * n + 1];
    const int cy = (int)(posy * (float)Hb);
    const int cx = (int)(posx * (float)Wb);

    for (int d = threadIdx.x; d < D; d += blockDim.x)
        sq[d] = qe[(size_t)n * D + d];
    __syncthreads();

    const int warp = threadIdx.x >> 5;
    const int lane = threadIdx.x & 31;
    const float4* sq4 = reinterpret_cast<const float4*>(sq);
    const float4 q0 = sq4[lane];
    const float4 q1 = sq4[lane + 32];

    float* out_logits = out;
    float* out_idx = out + (size_t)N * PP;

    for (int p = warp; p < PP; p += 8) {
        const int dy = p / PATCH - PATCH / 2;
        const int dx = p % PATCH - PATCH / 2;
        int y = cy + dy;
        int x = cx + dx;
        y = min(max(y, 0), Hb - 1);
        x = min(max(x, 0), Wb - 1);

        const size_t row_off = (((size_t)b * Hb + y) * Wb + x) * (size_t)D;
        const float4* row = reinterpret_cast<const float4*>(fm + row_off);

        const float4 f0 = row[lane];
        const float4 f1 = row[lane + 32];

        float s = f0.x * q0.x + f0.y * q0.y + f0.z * q0.z + f0.w * q0.w;
        s = fmaf(f1.x, q1.x, s);
        s = fmaf(f1.y, q1.y, s);
        s = fmaf(f1.z, q1.z, s);
        s = fmaf(f1.w, q1.w, s);

#pragma unroll
        for (int off = 16; off; off >>= 1)
            s += __shfl_xor_sync(0xFFFFFFFFu, s, off);

        if (lane == 0) {
            out_logits[(size_t)n * PP + p] = s;
            float4 iv = make_float4((float)b, (float)y, (float)x, (float)q);
            *reinterpret_cast<float4*>(&out_idx[((size_t)n * PP + p) * 4]) = iv;
        }
    }
}

extern "C" void kernel_launch(void* const* d_in, const int* in_sizes, int n_in,
                              void* d_out, int out_size) {
    const float* fm      = (const float*)d_in[0];
    const float* queries = (const float*)d_in[1];
    const float* qpos    = (const float*)d_in[2];
    const int*   shapes  = (const int*)d_in[4];
    const float* W0 = (const float*)d_in[5];
    const float* b0 = (const float*)d_in[6];
    const float* W1 = (const float*)d_in[7];
    const float* b1 = (const float*)d_in[8];
    const float* W2 = (const float*)d_in[9];
    const float* b2 = (const float*)d_in[10];
    const float* W3 = (const float*)d_in[11];
    const float* b3 = (const float*)d_in[12];

    const int B = in_sizes[3];               // query_batch_offsets length
    const int D = in_sizes[6];               // bias length
    const int N = in_sizes[1] / D;           // total queries
    const int Q = N / B;
    const int WSZ = D * D;                   // 65536 per layer

    float* act0;
    float* act1;
    float* whi;
    float* wlo;
    cudaGetSymbolAddress((void**)&act0, g_act0);
    cudaGetSymbolAddress((void**)&act1, g_act1);
    cudaGetSymbolAddress((void**)&whi, g_whi);
    cudaGetSymbolAddress((void**)&wlo, g_wlo);

    // Decompose weights (4 * 65536 floats, 1 float4 per thread)
    prep_kernel<<<(4 * WSZ / 4 + 255) / 256, 256>>>(W0, W1, W2, W3, whi, wlo);

    dim3 gblock(128);
    dim3 ggrid(D / BN, N / BM);              // (4, 32) = 128 blocks

    gemm_tf32_kernel<true ><<<ggrid, gblock>>>(queries, whi + 0 * WSZ, wlo + 0 * WSZ, b0, act0, N, D, D);
    gemm_tf32_kernel<true ><<<ggrid, gblock>>>(act0,    whi + 1 * WSZ, wlo + 1 * WSZ, b1, act1, N, D, D);
    gemm_tf32_kernel<true ><<<ggrid, gblock>>>(act1,    whi + 2 * WSZ, wlo + 2 * WSZ, b2, act0, N, D, D);
    gemm_tf32_kernel<false><<<ggrid, gblock>>>(act0,    whi + 3 * WSZ, wlo + 3 * WSZ, b3, act1, N, D, D);

    patch_kernel<<<N, 256>>>(fm, act1, qpos, shapes, (float*)d_out, N, Q, D);
}

// round 9
// speedup vs baseline: 1.2798x; 1.2798x over previous
#include <cuda_runtime.h>
#include <math.h>
#include <stdint.h>

#define PATCH 7
#define PP 49

// GEMM tiling: block 32x32 output, 4 warps (2x2), warp tile m16n16, BK=32.
#define NT_UNITS_A 256   // A frag units per k-tile: 4 kf * 2 mi * 32 lanes
#define NT_UNITS_B 512   // B frag units per k-tile: 4 kf * 4 nf * 32 lanes

// Scratch
__device__ float g_act0[1 << 18];    // activations ping (1024*256)
__device__ float g_act1[1 << 18];    // activations pong
__device__ float g_wf[1 << 19];      // 4 layers x fragment-ordered hi/lo weights

__device__ __forceinline__ uint32_t f32_to_tf32(float x) {
    uint32_t r;
    asm("cvt.rna.tf32.f32 %0, %1;" : "=r"(r) : "f"(x));
    return r;
}

__device__ __forceinline__ void mma_tf32(float* c, const uint32_t* a, uint32_t b0, uint32_t b1) {
    asm volatile(
        "mma.sync.aligned.m16n8k8.row.col.f32.tf32.tf32.f32 "
        "{%0,%1,%2,%3}, {%4,%5,%6,%7}, {%8,%9}, {%0,%1,%2,%3};\n"
        : "+f"(c[0]), "+f"(c[1]), "+f"(c[2]), "+f"(c[3])
        : "r"(a[0]), "r"(a[1]), "r"(a[2]), "r"(a[3]), "r"(b0), "r"(b1));
}

// ---------------------------------------------------------------------------
// prep_w: decompose W (4 layers, [K=256][N=256] each) into tf32 hi/lo and
// rearrange into fragment order:
//   Wf[layer][nb(8)][kt(8)][unit(512)] of float4 {bhi0, bhi1, blo0, blo1}
// where unit = (kf*4 + nf)*32 + lane, lane = g*4+tg,
//   bhi0/blo0 = W[kt*32+kf*8+tg   ][nb*32+nf*8+g]
//   bhi1/blo1 = W[kt*32+kf*8+tg+4 ][nb*32+nf*8+g]
// One block per (layer, nb, kt) tile. 256 threads.
// ---------------------------------------------------------------------------
__global__ void __launch_bounds__(256)
prep_w_kernel(const float* __restrict__ W0, const float* __restrict__ W1,
              const float* __restrict__ W2, const float* __restrict__ W3,
              float* __restrict__ Wf, int N) {
    __shared__ float tile[32][33];
    const int bid = blockIdx.x;
    const int layer = bid >> 6;
    const int nb = (bid >> 3) & 7;
    const int kt = bid & 7;
    const float* W = (layer == 0) ? W0 : (layer == 1) ? W1 : (layer == 2) ? W2 : W3;

    const int tid = threadIdx.x;
    // load 32x32 tile (rows = k, cols = n), coalesced float4
    {
        const int r = tid >> 3;
        const int c4 = (tid & 7) * 4;
        float4 w = *reinterpret_cast<const float4*>(&W[(size_t)(kt * 32 + r) * N + nb * 32 + c4]);
        tile[r][c4 + 0] = w.x;
        tile[r][c4 + 1] = w.y;
        tile[r][c4 + 2] = w.z;
        tile[r][c4 + 3] = w.w;
    }
    __syncthreads();

    float4* out = reinterpret_cast<float4*>(Wf) + (size_t)bid * NT_UNITS_B;
#pragma unroll
    for (int i = 0; i < 2; i++) {
        const int o = tid + i * 256;
        const int kf = o >> 7;
        const int nf = (o >> 5) & 3;
        const int lane = o & 31;
        const int g = lane >> 2;
        const int tg = lane & 3;
        const float w0 = tile[kf * 8 + tg][nf * 8 + g];
        const float w1 = tile[kf * 8 + tg + 4][nf * 8 + g];
        const float h0 = __uint_as_float(f32_to_tf32(w0));
        const float h1 = __uint_as_float(f32_to_tf32(w1));
        const float l0 = __uint_as_float(f32_to_tf32(w0 - h0));
        const float l1 = __uint_as_float(f32_to_tf32(w1 - h1));
        out[o] = make_float4(h0, h1, l0, l1);
    }
}

// ---------------------------------------------------------------------------
// 3xTF32 fragment-fed GEMM + bias (+ReLU): C[M,N] = A @ W + b
// Block 32x32 output, 128 threads (4 warps, 2x2), warp tile m16n16, BK=32.
// A gathered from plain fp32 + decomposed on the fly into fragment smem;
// B copied from pre-fragmented Wf. All fragment reads are 1x LDS.128.
// ---------------------------------------------------------------------------
template <bool RELU>
__global__ void __launch_bounds__(128)
gemm_frag_kernel(const float* __restrict__ A, const float* __restrict__ Wf,
                 const float* __restrict__ bias, float* __restrict__ C,
                 int M, int N, int K) {
    __shared__ float4 Ahi[2][NT_UNITS_A];
    __shared__ float4 Alo[2][NT_UNITS_A];
    __shared__ float4 Bf[2][NT_UNITS_B];

    const int tid = threadIdx.x;
    const int lane = tid & 31;
    const int wid = tid >> 5;
    const int warp_mi = wid & 1;       // m16 half
    const int wn = wid >> 1;           // n16 half -> nf base = wn*2
    const int g = lane >> 2;
    const int tg = lane & 3;

    const int bm = blockIdx.y * 32;
    const int bn = blockIdx.x * 32;
    const int nt = K / 32;             // 8

    // --- A gather mapping for this thread's 2 units ---
    int a_u[2], a_row0[2], a_kloc[2];
#pragma unroll
    for (int i = 0; i < 2; i++) {
        const int u = tid + i * 128;
        a_u[i] = u;
        const int kfmi = u >> 5;
        const int lu = u & 31;
        const int kf = kfmi >> 1;
        const int mi = kfmi & 1;
        a_row0[i] = bm + mi * 16 + (lu >> 2);
        a_kloc[i] = kf * 8 + (lu & 3);
    }

    const float4* wf_base = reinterpret_cast<const float4*>(Wf) + (size_t)blockIdx.x * nt * NT_UNITS_B;

    float4 bReg[4];
    float4 ahReg[2], alReg[2];

    auto g_load = [&](int t) {
        // B: 4 coalesced float4 per thread
        const float4* src = wf_base + (size_t)t * NT_UNITS_B;
#pragma unroll
        for (int i = 0; i < 4; i++) bReg[i] = src[tid + i * 128];
        // A: gather 4 scalars per unit, decompose
#pragma unroll
        for (int i = 0; i < 2; i++) {
            const int kcol = t * 32 + a_kloc[i];
            const float* p = &A[(size_t)a_row0[i] * K + kcol];
            const float x0 = p[0];
            const float x1 = p[8 * K];
            const float x2 = p[4];
            const float x3 = p[8 * K + 4];
            const float h0 = __uint_as_float(f32_to_tf32(x0));
            const float h1 = __uint_as_float(f32_to_tf32(x1));
            const float h2 = __uint_as_float(f32_to_tf32(x2));
            const float h3 = __uint_as_float(f32_to_tf32(x3));
            ahReg[i] = make_float4(h0, h1, h2, h3);
            alReg[i] = make_float4(__uint_as_float(f32_to_tf32(x0 - h0)),
                                   __uint_as_float(f32_to_tf32(x1 - h1)),
                                   __uint_as_float(f32_to_tf32(x2 - h2)),
                                   __uint_as_float(f32_to_tf32(x3 - h3)));
        }
    };
    auto s_store = [&](int buf) {
#pragma unroll
        for (int i = 0; i < 4; i++) Bf[buf][tid + i * 128] = bReg[i];
#pragma unroll
        for (int i = 0; i < 2; i++) {
            Ahi[buf][a_u[i]] = ahReg[i];
            Alo[buf][a_u[i]] = alReg[i];
        }
    };

    g_load(0);
    s_store(0);
    __syncthreads();

    float acc[2][4];
#pragma unroll
    for (int j = 0; j < 2; j++)
#pragma unroll
        for (int i = 0; i < 4; i++) acc[j][i] = 0.f;

    int cur = 0;
    for (int t = 0; t < nt; t++) {
        if (t + 1 < nt) g_load(t + 1);

#pragma unroll
        for (int kf = 0; kf < 4; kf++) {
            const float4 ah = Ahi[cur][(kf * 2 + warp_mi) * 32 + lane];
            const float4 al = Alo[cur][(kf * 2 + warp_mi) * 32 + lane];
            uint32_t ahi[4] = {__float_as_uint(ah.x), __float_as_uint(ah.y),
                               __float_as_uint(ah.z), __float_as_uint(ah.w)};
            uint32_t alo[4] = {__float_as_uint(al.x), __float_as_uint(al.y),
                               __float_as_uint(al.z), __float_as_uint(al.w)};
#pragma unroll
            for (int j = 0; j < 2; j++) {
                const int nf = wn * 2 + j;
                const float4 bv = Bf[cur][(kf * 4 + nf) * 32 + lane];
                const uint32_t bh0 = __float_as_uint(bv.x);
                const uint32_t bh1 = __float_as_uint(bv.y);
                const uint32_t bl0 = __float_as_uint(bv.z);
                const uint32_t bl1 = __float_as_uint(bv.w);
                mma_tf32(acc[j], ahi, bh0, bh1);
                mma_tf32(acc[j], ahi, bl0, bl1);
                mma_tf32(acc[j], alo, bh0, bh1);
            }
        }

        if (t + 1 < nt) {
            s_store(cur ^ 1);
            __syncthreads();
            cur ^= 1;
        }
    }

    // Epilogue
    const int row0 = bm + warp_mi * 16 + g;
#pragma unroll
    for (int j = 0; j < 2; j++) {
        const int col = bn + (wn * 2 + j) * 8 + 2 * tg;
        const float b0 = bias[col];
        const float b1 = bias[col + 1];
        float v0 = acc[j][0] + b0;
        float v1 = acc[j][1] + b1;
        float v2 = acc[j][2] + b0;
        float v3 = acc[j][3] + b1;
        if (RELU) {
            v0 = fmaxf(v0, 0.f);
            v1 = fmaxf(v1, 0.f);
            v2 = fmaxf(v2, 0.f);
            v3 = fmaxf(v3, 0.f);
        }
        *reinterpret_cast<float2*>(&C[(size_t)row0 * N + col]) = make_float2(v0, v1);
        *reinterpret_cast<float2*>(&C[(size_t)(row0 + 8) * N + col]) = make_float2(v2, v3);
    }
}

// ---------------------------------------------------------------------------
// Patch gather + dot + indices. One block (256 threads) per query.
// Output layout in d_out (float32):
//   [0, N*49)        logits (n, py, px)
//   [N*49, N*49*5)   indices as float (n, py, px, {b,y,x,q})
// ---------------------------------------------------------------------------
__global__ void __launch_bounds__(256)
patch_kernel(const float* __restrict__ fm, const float* __restrict__ qe,
             const float* __restrict__ qpos, const int* __restrict__ shapes,
             float* __restrict__ out, int N, int Q, int D) {
    __shared__ float sq[256];
    const int n = blockIdx.x;
    if (n >= N) return;

    const int b = n / Q;
    const int q = n - b * Q;
    const int Hb = shapes[2 * b + 0];
    const int Wb = shapes[2 * b + 1];

    const float posx = qpos[2 * n + 0];
    const float posy = qpos[2 * n + 1];
    const int cy = (int)(posy * (float)Hb);
    const int cx = (int)(posx * (float)Wb);

    for (int d = threadIdx.x; d < D; d += blockDim.x)
        sq[d] = qe[(size_t)n * D + d];
    __syncthreads();

    const int warp = threadIdx.x >> 5;
    const int lane = threadIdx.x & 31;
    const float4* sq4 = reinterpret_cast<const float4*>(sq);
    const float4 q0 = sq4[lane];
    const float4 q1 = sq4[lane + 32];

    float* out_logits = out;
    float* out_idx = out + (size_t)N * PP;

    for (int p = warp; p < PP; p += 8) {
        const int dy = p / PATCH - PATCH / 2;
        const int dx = p % PATCH - PATCH / 2;
        int y = cy + dy;
        int x = cx + dx;
        y = min(max(y, 0), Hb - 1);
        x = min(max(x, 0), Wb - 1);

        const size_t row_off = (((size_t)b * Hb + y) * Wb + x) * (size_t)D;
        const float4* row = reinterpret_cast<const float4*>(fm + row_off);

        const float4 f0 = row[lane];
        const float4 f1 = row[lane + 32];

        float s = f0.x * q0.x + f0.y * q0.y + f0.z * q0.z + f0.w * q0.w;
        s = fmaf(f1.x, q1.x, s);
        s = fmaf(f1.y, q1.y, s);
        s = fmaf(f1.z, q1.z, s);
        s = fmaf(f1.w, q1.w, s);

#pragma unroll
        for (int off = 16; off; off >>= 1)
            s += __shfl_xor_sync(0xFFFFFFFFu, s, off);

        if (lane == 0) {
            out_logits[(size_t)n * PP + p] = s;
            float4 iv = make_float4((float)b, (float)y, (float)x, (float)q);
            *reinterpret_cast<float4*>(&out_idx[((size_t)n * PP + p) * 4]) = iv;
        }
    }
}

extern "C" void kernel_launch(void* const* d_in, const int* in_sizes, int n_in,
                              void* d_out, int out_size) {
    const float* fm      = (const float*)d_in[0];
    const float* queries = (const float*)d_in[1];
    const float* qpos    = (const float*)d_in[2];
    const int*   shapes  = (const int*)d_in[4];
    const float* W0 = (const float*)d_in[5];
    const float* b0 = (const float*)d_in[6];
    const float* W1 = (const float*)d_in[7];
    const float* b1 = (const float*)d_in[8];
    const float* W2 = (const float*)d_in[9];
    const float* b2 = (const float*)d_in[10];
    const float* W3 = (const float*)d_in[11];
    const float* b3 = (const float*)d_in[12];

    const int B = in_sizes[3];               // query_batch_offsets length
    const int D = in_sizes[6];               // bias length (256)
    const int N = in_sizes[1] / D;           // total queries (1024)
    const int Q = N / B;
    const int LSZ = (D / 32) * (D / 32) * NT_UNITS_B * 4;  // floats per layer in Wf

    float* act0;
    float* act1;
    float* wf;
    cudaGetSymbolAddress((void**)&act0, g_act0);
    cudaGetSymbolAddress((void**)&act1, g_act1);
    cudaGetSymbolAddress((void**)&wf, g_wf);

    // Fragment-order weight decomposition: 4 layers x 8 nb x 8 kt blocks
    prep_w_kernel<<<4 * (D / 32) * (D / 32), 256>>>(W0, W1, W2, W3, wf, D);

    dim3 gblock(128);
    dim3 ggrid(D / 32, N / 32);              // (8, 32) = 256 blocks

    gemm_frag_kernel<true ><<<ggrid, gblock>>>(queries, wf + 0 * LSZ, b0, act0, N, D, D);
    gemm_frag_kernel<true ><<<ggrid, gblock>>>(act0,    wf + 1 * LSZ, b1, act1, N, D, D);
    gemm_frag_kernel<true ><<<ggrid, gblock>>>(act1,    wf + 2 * LSZ, b2, act0, N, D, D);
    gemm_frag_kernel<false><<<ggrid, gblock>>>(act0,    wf + 3 * LSZ, b3, act1, N, D, D);

    patch_kernel<<<N, 256>>>(fm, act1, qpos, shapes, (float*)d_out, N, Q, D);
}